// round 1
// baseline (speedup 1.0000x reference)
#include <cuda_runtime.h>
#include <cuda_bf16.h>

// Problem constants
#define NLAT   8192     // latents per tensor
#define NSMP   2048     // samples per tensor
#define ES     64       // state embedding dim
#define EA     32       // action embedding dim
#define TAILK  4        // selection_tail_size == pushing_sample_size
#define FARK   64       // far_sample_count
#define NSL    32       // latent slices
#define LPS    (NLAT / NSL)   // 256 latents per slice
#define TPB    256      // threads per block (each thread = one sample)
#define SCHUNK (NSMP / TPB)   // 8 sample chunks

#define FLT_BIG 3.402823466e+38f

// ---------------- scratch (device globals; no allocation allowed) ----------
__device__ float g_pt4[2][NSL * NSMP * 4];   // [tensor][slice][sample][4]
__device__ float g_tail[2][NSMP];
__device__ float g_sq[2][NSMP];
__device__ float g_selsq[2][NSMP];
__device__ float g_sizes[2];

// branchless sorted insert: keep m0<=m1<=m2<=m3 the 4 smallest seen
__device__ __forceinline__ void ins4(float d, float& m0, float& m1, float& m2, float& m3) {
    float lo, hi;
    lo = fminf(m0, d);  hi = fmaxf(m0, d);  m0 = lo;
    lo = fminf(m1, hi); hi = fmaxf(m1, hi); m1 = lo;
    lo = fminf(m2, hi); hi = fmaxf(m2, hi); m2 = lo;
    m3 = fminf(m3, hi);
}

// ---------------- size loss: mean(relu(L1norm - 1)^2) over 8192 rows -------
template<int E>
__device__ __forceinline__ float size_accum(const float* __restrict__ lat, int tid) {
    float acc = 0.0f;
    for (int r = tid; r < NLAT; r += TPB) {
        const float* row = lat + r * E;
        float a0 = 0.f, a1 = 0.f, a2 = 0.f, a3 = 0.f;
        #pragma unroll
        for (int k = 0; k < E; k += 4) {
            float4 v = *(const float4*)(row + k);
            a0 += fabsf(v.x); a1 += fabsf(v.y); a2 += fabsf(v.z); a3 += fabsf(v.w);
        }
        float n = (a0 + a1) + (a2 + a3);
        float viol = fmaxf(n - 1.0f, 0.0f);   // STATE/ACTION_SPACE_SIZE == 1.0
        acc += viol * viol;
    }
    return acc;
}

__global__ void size_loss_kernel(const float* __restrict__ lat_s,
                                 const float* __restrict__ lat_a) {
    __shared__ float red[TPB];
    const int tid = threadIdx.x;
    float acc = (blockIdx.x == 0) ? size_accum<ES>(lat_s, tid)
                                  : size_accum<EA>(lat_a, tid);
    red[tid] = acc;
    __syncthreads();
    for (int st = TPB / 2; st > 0; st >>= 1) {
        if (tid < st) red[tid] += red[tid + st];
        __syncthreads();
    }
    if (tid == 0) g_sizes[blockIdx.x] = red[0] / (float)NLAT;
}

// ---------------- coverage partial top-4 -----------------------------------
// grid: (SCHUNK, NSL). Each thread owns one sample (row in registers),
// iterates over this block's latent slice streamed through smem tiles.
template<int E, int TN, int SEL>
__global__ void __launch_bounds__(TPB, 2)
cov_partial_kernel(const float* __restrict__ samples,
                   const float* __restrict__ latents) {
    __shared__ __align__(16) float tile[TN * E];
    const int tid   = threadIdx.x;
    const int s     = blockIdx.x * TPB + tid;
    const int slice = blockIdx.y;
    const int lat0  = slice * LPS;

    // sample row -> registers
    float q[E];
    #pragma unroll
    for (int k = 0; k < E; k += 4) {
        float4 v = *(const float4*)(samples + s * E + k);
        q[k] = v.x; q[k + 1] = v.y; q[k + 2] = v.z; q[k + 3] = v.w;
    }

    float m0 = FLT_BIG, m1 = FLT_BIG, m2 = FLT_BIG, m3 = FLT_BIG;

    for (int t0 = 0; t0 < LPS; t0 += TN) {
        __syncthreads();
        // cooperative tile load: TN*E floats, coalesced float4
        const float* src = latents + (lat0 + t0) * E;
        #pragma unroll
        for (int i = tid * 4; i < TN * E; i += TPB * 4) {
            *(float4*)(tile + i) = *(const float4*)(src + i);
        }
        __syncthreads();

        #pragma unroll 1
        for (int n = 0; n < TN; n++) {
            const float* lr = tile + n * E;   // all lanes same addr -> LDS broadcast
            float a0 = 0.f, a1 = 0.f, a2 = 0.f, a3 = 0.f;
            #pragma unroll
            for (int k = 0; k < E; k += 4) {
                float4 v = *(const float4*)(lr + k);
                a0 += fabsf(q[k]     - v.x);
                a1 += fabsf(q[k + 1] - v.y);
                a2 += fabsf(q[k + 2] - v.z);
                a3 += fabsf(q[k + 3] - v.w);
            }
            float d = (a0 + a1) + (a2 + a3);
            ins4(d, m0, m1, m2, m3);
        }
    }

    // layout [slice][sample][4] -> coalesced float4 store & merge reads
    *(float4*)(&g_pt4[SEL][(slice * NSMP + s) * 4]) = make_float4(m0, m1, m2, m3);
}

// ---------------- merge partial top-4 across slices ------------------------
// grid: (NSMP/TPB, 2). One thread per sample.
__global__ void cov_merge_kernel() {
    const int sel = blockIdx.y;
    const int s   = blockIdx.x * TPB + threadIdx.x;
    float m0 = FLT_BIG, m1 = FLT_BIG, m2 = FLT_BIG, m3 = FLT_BIG;
    const float* base = g_pt4[sel];
    #pragma unroll 4
    for (int sl = 0; sl < NSL; sl++) {
        float4 v = *(const float4*)(base + (sl * NSMP + s) * 4);
        ins4(v.x, m0, m1, m2, m3);
        ins4(v.y, m0, m1, m2, m3);
        ins4(v.z, m0, m1, m2, m3);
        ins4(v.w, m0, m1, m2, m3);
    }
    g_tail[sel][s] = 0.25f * ((m0 + m1) + (m2 + m3));
    g_sq[sel][s]   = (m0 * m0 + m1 * m1) + (m2 * m2 + m3 * m3);
}

// ---------------- rank: select top-64 tails (stable, matching lax.top_k) ---
// grid: (NSMP/TPB, 2). Count strictly-better entries; <64 -> selected.
__global__ void rank_select_kernel() {
    __shared__ float t[NSMP];
    const int sel = blockIdx.y;
    const int tid = threadIdx.x;
    for (int i = tid; i < NSMP; i += TPB) t[i] = g_tail[sel][i];
    __syncthreads();

    const int i  = blockIdx.x * TPB + tid;
    const float ti = t[i];
    int cnt = 0;
    #pragma unroll 8
    for (int j = 0; j < NSMP; j++) {
        float tj = t[j];
        cnt += (tj > ti) || (tj == ti && j < i);
    }
    g_selsq[sel][i] = (cnt < FARK) ? g_sq[sel][i] : 0.0f;
}

// ---------------- final combine (deterministic fixed-order reduce) ---------
__global__ void combine_kernel(float* __restrict__ out) {
    __shared__ float red[TPB];
    const int tid = threadIdx.x;
    float acc = 0.0f;
    for (int i = tid; i < NSMP; i += TPB)
        acc += g_selsq[0][i] + g_selsq[1][i];
    red[tid] = acc;
    __syncthreads();
    for (int st = TPB / 2; st > 0; st >>= 1) {
        if (tid < st) red[tid] += red[tid + st];
        __syncthreads();
    }
    if (tid == 0)
        out[0] = g_sizes[0] + g_sizes[1] + red[0] / (float)(FARK * TAILK);
}

// ---------------- launch ----------------------------------------------------
extern "C" void kernel_launch(void* const* d_in, const int* in_sizes, int n_in,
                              void* d_out, int out_size) {
    const float* lat_s = (const float*)d_in[0];   // latent_states   [8192,64]
    const float* lat_a = (const float*)d_in[1];   // latent_actions  [8192,32]
    const float* smp_s = (const float*)d_in[2];   // state samples   [2048,64]
    const float* smp_a = (const float*)d_in[3];   // action samples  [2048,32]
    float* out = (float*)d_out;

    size_loss_kernel<<<2, TPB>>>(lat_s, lat_a);
    cov_partial_kernel<ES, 64, 0><<<dim3(SCHUNK, NSL), TPB>>>(smp_s, lat_s);
    cov_partial_kernel<EA, 128, 1><<<dim3(SCHUNK, NSL), TPB>>>(smp_a, lat_a);
    cov_merge_kernel<<<dim3(SCHUNK, 2), TPB>>>();
    rank_select_kernel<<<dim3(SCHUNK, 2), TPB>>>();
    combine_kernel<<<1, TPB>>>(out);
}